// round 14
// baseline (speedup 1.0000x reference)
#include <cuda_runtime.h>
#include <cuda_bf16.h>
#include <math.h>
#include <stdint.h>

#define BATCH 2
#define SEQ   2048
#define EMB   2048
#define NH    16
#define HD    128
#define NQKV  6144
#define MROWS 4096
#define GK    2048
#define NSTG8 (GK / 32)     // 64 k32 stages

// ---------------- scratch (no allocation allowed) ----------------
__device__ float g_q[BATCH * NH * SEQ * HD];     // fp32 Q pre-rope; later attn output
__device__ float g_k[BATCH * NH * SEQ * HD];     // fp32 K pre-rope

__device__ __nv_bfloat16 g_qhi[BATCH * NH * SEQ * HD];
__device__ __nv_bfloat16 g_qlo[BATCH * NH * SEQ * HD];
__device__ __nv_bfloat16 g_khi[BATCH * NH * SEQ * HD];
__device__ __nv_bfloat16 g_klo[BATCH * NH * SEQ * HD];
__device__ __nv_bfloat16 g_vhi[BATCH * NH * SEQ * HD];
__device__ __nv_bfloat16 g_vlo[BATCH * NH * SEQ * HD];

// int8 operand storage
__device__ int8_t g_a0[MROWS * GK];       // X / attn-out level 0
__device__ int8_t g_a1[MROWS * GK];       // level 1 (residual * 128)
__device__ float  g_sa[MROWS];
__device__ int8_t g_w10[NQKV * GK];
__device__ int8_t g_w11[NQKV * GK];
__device__ float  g_sw1[NQKV];
__device__ int8_t g_w20[EMB * GK];
__device__ int8_t g_w21[EMB * GK];
__device__ float  g_sw2[EMB];

__device__ float g_cs[SEQ * HD];
__device__ float g_sn[SEQ * HD];

// ================= family-generic PTX helpers ====================
__device__ __forceinline__ uint32_t smem_u32(const void* p) {
    uint32_t a;
    asm("{ .reg .u64 t; cvta.to.shared.u64 t, %1; cvt.u32.u64 %0, t; }" : "=r"(a) : "l"(p));
    return a;
}
#define CP_ASYNC16(s, g) \
    asm volatile("cp.async.cg.shared.global [%0], [%1], 16;" :: "r"(s), "l"(g))
#define CP_COMMIT() asm volatile("cp.async.commit_group;" ::: "memory")
#define CP_WAIT1()  asm volatile("cp.async.wait_group 1;" ::: "memory")
#define CP_WAIT0()  asm volatile("cp.async.wait_group 0;" ::: "memory")

__device__ __forceinline__ void ldsm4(uint32_t* r, uint32_t addr) {
    asm volatile("ldmatrix.sync.aligned.m8n8.x4.shared.b16 {%0,%1,%2,%3}, [%4];"
        : "=r"(r[0]), "=r"(r[1]), "=r"(r[2]), "=r"(r[3]) : "r"(addr));
}
__device__ __forceinline__ void ldsm4t(uint32_t* r, uint32_t addr) {
    asm volatile("ldmatrix.sync.aligned.m8n8.x4.trans.shared.b16 {%0,%1,%2,%3}, [%4];"
        : "=r"(r[0]), "=r"(r[1]), "=r"(r[2]), "=r"(r[3]) : "r"(addr));
}
__device__ __forceinline__ void mma_bf16(float* c, const uint32_t* a, const uint32_t* b) {
    asm volatile(
        "mma.sync.aligned.m16n8k16.row.col.f32.bf16.bf16.f32 "
        "{%0,%1,%2,%3}, {%4,%5,%6,%7}, {%8,%9}, {%0,%1,%2,%3};"
        : "+f"(c[0]), "+f"(c[1]), "+f"(c[2]), "+f"(c[3])
        : "r"(a[0]), "r"(a[1]), "r"(a[2]), "r"(a[3]), "r"(b[0]), "r"(b[1]));
}
__device__ __forceinline__ void mma_s8(int* c, const uint32_t* a, const uint32_t* b) {
    asm volatile(
        "mma.sync.aligned.m16n8k32.row.col.s32.s8.s8.s32 "
        "{%0,%1,%2,%3}, {%4,%5,%6,%7}, {%8,%9}, {%0,%1,%2,%3};"
        : "+r"(c[0]), "+r"(c[1]), "+r"(c[2]), "+r"(c[3])
        : "r"(a[0]), "r"(a[1]), "r"(a[2]), "r"(a[3]), "r"(b[0]), "r"(b[1]));
}
__device__ __forceinline__ uint32_t packbf(float a, float b) {
    __nv_bfloat162 t;
    t.x = __float2bfloat16(a);
    t.y = __float2bfloat16(b);
    return *reinterpret_cast<uint32_t*>(&t);
}

// ============ fp32 -> 2-level int8 row quantization ==============
// x = s*(q0 + q1/128) + eps, |eps| <= s/256, s = rowmax/127
__global__ void __launch_bounds__(256)
quant_rows(const float* __restrict__ x, int8_t* __restrict__ q0,
           int8_t* __restrict__ q1, float* __restrict__ sc, int ncols)
{
    __shared__ float red[8];
    const int row = blockIdx.x;
    const int tid = threadIdx.x;
    const float* xr = x + (size_t)row * ncols;

    float m = 0.f;
    for (int c = tid * 4; c < ncols; c += 1024) {
        float4 v = *(const float4*)(xr + c);
        m = fmaxf(m, fmaxf(fmaxf(fabsf(v.x), fabsf(v.y)), fmaxf(fabsf(v.z), fabsf(v.w))));
    }
#pragma unroll
    for (int o = 16; o > 0; o >>= 1) m = fmaxf(m, __shfl_xor_sync(0xffffffffu, m, o));
    if ((tid & 31) == 0) red[tid >> 5] = m;
    __syncthreads();
    if (tid < 32) {
        float t = (tid < 8) ? red[tid] : 0.f;
#pragma unroll
        for (int o = 4; o > 0; o >>= 1) t = fmaxf(t, __shfl_xor_sync(0xffffffffu, t, o));
        if (tid == 0) red[0] = t;
    }
    __syncthreads();
    const float s = fmaxf(red[0], 1e-20f) / 127.f;
    const float inv = 1.f / s;
    if (tid == 0) sc[row] = s;

    for (int c = tid * 4; c < ncols; c += 1024) {
        float4 v = *(const float4*)(xr + c);
        float r0 = v.x * inv, r1 = v.y * inv, r2 = v.z * inv, r3 = v.w * inv;
        float a0 = rintf(r0), a1 = rintf(r1), a2 = rintf(r2), a3 = rintf(r3);
        char4 lo, hi;
        hi.x = (char)(int)a0; hi.y = (char)(int)a1;
        hi.z = (char)(int)a2; hi.w = (char)(int)a3;
        lo.x = (char)(int)rintf((r0 - a0) * 128.f);
        lo.y = (char)(int)rintf((r1 - a1) * 128.f);
        lo.z = (char)(int)rintf((r2 - a2) * 128.f);
        lo.w = (char)(int)rintf((r3 - a3) * 128.f);
        *(char4*)(q0 + (size_t)row * ncols + c) = hi;
        *(char4*)(q1 + (size_t)row * ncols + c) = lo;
    }
}

// =================================================================
// int8 2-level GEMM: C[M,N] = sa_i*sb_j*(A0B0 + (A0B1+A1B0)/128) + bias
// CTA tile 128x128, 8 warps (2x4) of 64x32, k32 per stage, 64 stages,
// double-buffered cp.async. 48 s8-MMAs per warp-stage.
// MODE 0: row-major C     MODE 1: scatter Q/K fp32, V bf16 hi/lo
// =================================================================
#define I8ROW 48                  // 32 data + 16 pad bytes
#define I8TILE (128 * I8ROW)      // 6144 B per matrix
#define I8STAGE (4 * I8TILE)      // 24576 B (A0,A1,B0,B1)
#define GEMM_SMEM (2 * I8STAGE)   // 49152 B

template <int MODE>
__global__ void __launch_bounds__(256, 1)
gemm_i8(const int8_t* __restrict__ A0, const int8_t* __restrict__ A1,
        const float* __restrict__ sa,
        const int8_t* __restrict__ B0, const int8_t* __restrict__ B1,
        const float* __restrict__ sb,
        const float* __restrict__ bias, float* __restrict__ C, int Ndim)
{
    extern __shared__ char smem[];
    const uint32_t sbm = smem_u32(smem);
    const int tid = threadIdx.x;
    const int lane = tid & 31, wid = tid >> 5;
    const int wm = wid >> 2, wn = wid & 3;          // 2 x 4 warp grid
    const int bm = blockIdx.y * 128, bn = blockIdx.x * 128;

    const char* gA0 = (const char*)(A0 + (size_t)bm * GK);
    const char* gA1 = (const char*)(A1 + (size_t)bm * GK);
    const char* gB0 = (const char*)(B0 + (size_t)bn * GK);
    const char* gB1 = (const char*)(B1 + (size_t)bn * GK);

    // ldmatrix fragment offsets (b16 view of int8 pairs)
    uint32_t arow[4];
#pragma unroll
    for (int mt = 0; mt < 4; ++mt)
        arow[mt] = (uint32_t)((wm * 64 + mt * 16 + (lane & 15)) * I8ROW + ((lane >> 4) << 4));
    uint32_t brow[2];
#pragma unroll
    for (int nb = 0; nb < 2; ++nb)
        brow[nb] = (uint32_t)((wn * 32 + nb * 16 + ((lane >> 4) << 3) + (lane & 7)) * I8ROW
                              + (((lane >> 3) & 1) << 4));

    int accM[4][4][4], accC[4][4][4];
#pragma unroll
    for (int i = 0; i < 4; ++i)
#pragma unroll
        for (int j = 0; j < 4; ++j)
#pragma unroll
            for (int k = 0; k < 4; ++k) { accM[i][j][k] = 0; accC[i][j][k] = 0; }

    // loader: per matrix 128 rows x 2 16B-chunks = 256 chunks
    const int lrow = tid >> 1;
    const int lseg = (tid & 1) * 16;
    auto issue_load = [&](int stage, int buf) {
        const size_t kb = (size_t)stage * 32 + lseg;
        const uint32_t base = sbm + buf * I8STAGE + lrow * I8ROW + lseg;
        const size_t go = (size_t)lrow * GK + kb;
        CP_ASYNC16(base + 0 * I8TILE, gA0 + go);
        CP_ASYNC16(base + 1 * I8TILE, gA1 + go);
        CP_ASYNC16(base + 2 * I8TILE, gB0 + go);
        CP_ASYNC16(base + 3 * I8TILE, gB1 + go);
        CP_COMMIT();
    };

    issue_load(0, 0);

    for (int s = 0; s < NSTG8; ++s) {
        if (s + 1 < NSTG8) {
            issue_load(s + 1, (s + 1) & 1);
            CP_WAIT1();
        } else {
            CP_WAIT0();
        }
        __syncthreads();

        const uint32_t base = sbm + (s & 1) * I8STAGE;
        uint32_t b0f[2][4], b1f[2][4];
#pragma unroll
        for (int nb = 0; nb < 2; ++nb) {
            ldsm4(b0f[nb], base + 2 * I8TILE + brow[nb]);
            ldsm4(b1f[nb], base + 3 * I8TILE + brow[nb]);
        }
#pragma unroll
        for (int mt = 0; mt < 4; ++mt) {
            uint32_t a0f[4], a1f[4];
            ldsm4(a0f, base + 0 * I8TILE + arow[mt]);
            ldsm4(a1f, base + 1 * I8TILE + arow[mt]);
#pragma unroll
            for (int j = 0; j < 4; ++j) {
                const int nb = j >> 1, off = (j & 1) * 2;
                mma_s8(accM[mt][j], a0f, &b0f[nb][off]);
                mma_s8(accC[mt][j], a0f, &b1f[nb][off]);
                mma_s8(accC[mt][j], a1f, &b0f[nb][off]);
            }
        }
        __syncthreads();
    }

    // ---------------- epilogue ----------------
#pragma unroll
    for (int mt = 0; mt < 4; ++mt) {
        const int gm0 = bm + wm * 64 + mt * 16 + (lane >> 2);
        const float sa0 = sa[gm0], sa1 = sa[gm0 + 8];
#pragma unroll
        for (int j = 0; j < 4; ++j) {
            const int gn = bn + wn * 32 + j * 8 + (lane & 3) * 2;
            const float2 bv = *(const float2*)(bias + gn);
            const float2 sbv = *(const float2*)(sb + gn);
            float2 v0, v1;
            v0.x = sa0 * sbv.x * ((float)accM[mt][j][0] + (float)accC[mt][j][0] * 0.0078125f) + bv.x;
            v0.y = sa0 * sbv.y * ((float)accM[mt][j][1] + (float)accC[mt][j][1] * 0.0078125f) + bv.y;
            v1.x = sa1 * sbv.x * ((float)accM[mt][j][2] + (float)accC[mt][j][2] * 0.0078125f) + bv.x;
            v1.y = sa1 * sbv.y * ((float)accM[mt][j][3] + (float)accC[mt][j][3] * 0.0078125f) + bv.y;
            if (MODE == 0) {
                *(float2*)(C + (size_t)gm0 * Ndim + gn)       = v0;
                *(float2*)(C + (size_t)(gm0 + 8) * Ndim + gn) = v1;
            } else {
                const int which = gn >> 11;                  // 0=Q,1=K,2=V
                const int hh = (gn >> 7) & 15;
                const int dd = (gn & 127);
                const int b0 = gm0 >> 11, s0 = gm0 & 2047;
                const int gm1 = gm0 + 8;
                const int b1 = gm1 >> 11, s1 = gm1 & 2047;
                const size_t o0 = (((size_t)(b0 * NH + hh) * SEQ + s0) * HD) + dd;
                const size_t o1 = (((size_t)(b1 * NH + hh) * SEQ + s1) * HD) + dd;
                if (which == 2) {
                    float h0 = __bfloat162float(__float2bfloat16(v0.x));
                    float h1 = __bfloat162float(__float2bfloat16(v0.y));
                    float h2 = __bfloat162float(__float2bfloat16(v1.x));
                    float h3 = __bfloat162float(__float2bfloat16(v1.y));
                    *(uint32_t*)(g_vhi + o0) = packbf(v0.x, v0.y);
                    *(uint32_t*)(g_vlo + o0) = packbf(v0.x - h0, v0.y - h1);
                    *(uint32_t*)(g_vhi + o1) = packbf(v1.x, v1.y);
                    *(uint32_t*)(g_vlo + o1) = packbf(v1.x - h2, v1.y - h3);
                } else {
                    float* tgt = (which == 0) ? g_q : g_k;
                    *(float2*)(tgt + o0) = v0;
                    *(float2*)(tgt + o1) = v1;
                }
            }
        }
    }
}

// =================================================================
// RoPE: table once (double precision), then fp32 apply + bf16 split.
// =================================================================
__global__ void rope_table()
{
    const int s = blockIdx.x, d = threadIdx.x;
    const int i = d >> 1;
    const double ang = exp(-((double)(2 * i) / 2048.0) * 9.210340371976184);
    const double fr = (double)s * ang;
    g_cs[s * HD + d] = (float)cos(fr);
    g_sn[s * HD + d] = (float)sin(fr);
}

__global__ void rope_apply()
{
    __shared__ float rq[HD], rk[HD];
    const int row = blockIdx.x;            // (b*NH+h)*SEQ + s
    const int s = row & (SEQ - 1);
    const int d = threadIdx.x;
    rq[d] = g_q[(size_t)row * HD + d];
    rk[d] = g_k[(size_t)row * HD + d];
    __syncthreads();

    const float c  = g_cs[s * HD + d];
    const float sn = g_sn[s * HD + d];
    float oq, ok;
    if (d < 64) {
        oq = c * rq[d] - sn * rq[2 * d + 1];
        ok = c * rk[d] - sn * rk[2 * d + 1];
    } else {
        const int j = d - 64;
        oq = c * rq[d] + sn * rq[2 * j];
        ok = c * rk[d] + sn * rk[2 * j];
    }
    const float qs = oq * 0.08838834764831845f;   // fold 1/sqrt(HD)
    const size_t idx = (size_t)row * HD + d;
    __nv_bfloat16 qh = __float2bfloat16(qs);
    g_qhi[idx] = qh;
    g_qlo[idx] = __float2bfloat16(qs - __bfloat162float(qh));
    __nv_bfloat16 kh = __float2bfloat16(ok);
    g_khi[idx] = kh;
    g_klo[idx] = __float2bfloat16(ok - __bfloat162float(kh));
}

// =================================================================
// MMA flash attention, bf16x3, Q fragments in registers.
// Output: fp32 into g_q (reused as attn-out [b,s,h*HD+d]).
// =================================================================
#define AKB   32
#define QROWB 272
#define PROWB 80
#define KSTGB (AKB * QROWB)
#define OFF_QHI 0
#define OFF_QLO 34816
#define OFF_KHI 69632
#define OFF_KLO (OFF_KHI + 2 * KSTGB)
#define OFF_VHI (OFF_KLO + 2 * KSTGB)
#define OFF_VLO (OFF_VHI + 2 * KSTGB)
#define OFF_PHI (OFF_VLO + 2 * KSTGB)
#define OFF_PLO (OFF_PHI + 128 * PROWB)
#define OFF_MSK (OFF_PLO + 128 * PROWB)
#define ATTN_SMEM (OFF_MSK + 128)

__global__ void __launch_bounds__(256, 1)
attn_mma(const int* __restrict__ mask)
{
    extern __shared__ char smem[];
    const uint32_t sb = smem_u32(smem);
    const int tid = threadIdx.x;
    const int lane = tid & 31, wm = tid >> 5;
    const int q0 = blockIdx.x * 128;
    const int h = blockIdx.y, b = blockIdx.z;
    const size_t bh = ((size_t)b * NH + h) * SEQ;

    // ---- load Q tile (hi+lo) ----
    {
        const char* gqh = (const char*)(g_qhi + (bh + q0) * HD);
        const char* gql = (const char*)(g_qlo + (bh + q0) * HD);
#pragma unroll
        for (int i = 0; i < 8; ++i) {
            const int c = tid + i * 256;
            const int row = c >> 4, seg = (c & 15) * 16;
            CP_ASYNC16(sb + OFF_QHI + row * QROWB + seg, gqh + (size_t)row * 256 + seg);
            CP_ASYNC16(sb + OFF_QLO + row * QROWB + seg, gql + (size_t)row * 256 + seg);
        }
        CP_COMMIT();
    }
    auto loadKV = [&](int kt) {
        const int st = kt & 1;
        const char* gkh = (const char*)(g_khi + (bh + kt * AKB) * HD);
        const char* gkl = (const char*)(g_klo + (bh + kt * AKB) * HD);
        const char* gvh = (const char*)(g_vhi + (bh + kt * AKB) * HD);
        const char* gvl = (const char*)(g_vlo + (bh + kt * AKB) * HD);
#pragma unroll
        for (int i = 0; i < 2; ++i) {
            const int c = tid + i * 256;
            const int row = c >> 4, seg = (c & 15) * 16;
            const uint32_t so = st * KSTGB + row * QROWB + seg;
            const size_t go = (size_t)row * 256 + seg;
            CP_ASYNC16(sb + OFF_KHI + so, gkh + go);
            CP_ASYNC16(sb + OFF_KLO + so, gkl + go);
            CP_ASYNC16(sb + OFF_VHI + so, gvh + go);
            CP_ASYNC16(sb + OFF_VLO + so, gvl + go);
        }
        CP_COMMIT();
    };
    loadKV(0);

    const int r0 = lane >> 2;
    const uint32_t qoff = (wm * 16 + (lane & 15)) * QROWB + ((lane >> 4) << 4);
    const uint32_t kfr = (((lane >> 4) << 3) + (lane & 7)) * QROWB + (((lane >> 3) & 1) << 4);
    const uint32_t poff = (wm * 16 + (lane & 15)) * PROWB + ((lane >> 4) << 4);
    const uint32_t vfr = (lane & 15) * QROWB + (((lane >> 4) << 3) << 1);

    CP_WAIT1();
    __syncthreads();
    uint32_t qh[8][4], ql[8][4];
#pragma unroll
    for (int ks = 0; ks < 8; ++ks) {
        ldsm4(qh[ks], sb + OFF_QHI + qoff + ks * 32);
        ldsm4(ql[ks], sb + OFF_QLO + qoff + ks * 32);
    }

    float o[16][4];
#pragma unroll
    for (int t = 0; t < 16; ++t)
#pragma unroll
        for (int j = 0; j < 4; ++j) o[t][j] = 0.f;
    float m0 = -INFINITY, m1 = -INFINITY, l0 = 0.f, l1 = 0.f;

    float* msk = (float*)(smem + OFF_MSK);

    for (int kt = 0; kt < SEQ / AKB; ++kt) {
        __syncthreads();
        if (kt + 1 < SEQ / AKB) loadKV(kt + 1);
        if (tid < AKB) msk[tid] = (float)mask[b * SEQ + kt * AKB + tid];
        if (kt + 1 < SEQ / AKB) { CP_WAIT1(); } else { CP_WAIT0(); }
        __syncthreads();

        const uint32_t kbh = sb + OFF_KHI + (kt & 1) * KSTGB;
        const uint32_t kbl = sb + OFF_KLO + (kt & 1) * KSTGB;

        float s[4][4];
#pragma unroll
        for (int t = 0; t < 4; ++t)
#pragma unroll
            for (int j = 0; j < 4; ++j) s[t][j] = 0.f;
#pragma unroll
        for (int ks = 0; ks < 8; ++ks) {
            uint32_t kh[2][4], kl[2][4];
#pragma unroll
            for (int nb = 0; nb < 2; ++nb) {
                ldsm4(kh[nb], kbh + nb * 16 * QROWB + kfr + ks * 32);
                ldsm4(kl[nb], kbl + nb * 16 * QROWB + kfr + ks * 32);
            }
#pragma unroll
            for (int t = 0; t < 4; ++t) {
                const int nb = t >> 1, off = (t & 1) * 2;
                mma_bf16(s[t], qh[ks], &kh[nb][off]);
                mma_bf16(s[t], qh[ks], &kl[nb][off]);
                mma_bf16(s[t], ql[ks], &kh[nb][off]);
            }
        }

        float rm0 = -INFINITY, rm1 = -INFINITY;
#pragma unroll
        for (int t = 0; t < 4; ++t) {
            const int c = t * 8 + (lane & 3) * 2;
            const float k0 = msk[c], k1 = msk[c + 1];
            if (k0 == 0.f) { s[t][0] = -1e9f; s[t][2] = -1e9f; }
            if (k1 == 0.f) { s[t][1] = -1e9f; s[t][3] = -1e9f; }
            rm0 = fmaxf(rm0, fmaxf(s[t][0], s[t][1]));
            rm1 = fmaxf(rm1, fmaxf(s[t][2], s[t][3]));
        }
        rm0 = fmaxf(rm0, __shfl_xor_sync(0xffffffffu, rm0, 1));
        rm0 = fmaxf(rm0, __shfl_xor_sync(0xffffffffu, rm0, 2));
        rm1 = fmaxf(rm1, __shfl_xor_sync(0xffffffffu, rm1, 1));
        rm1 = fmaxf(rm1, __shfl_xor_sync(0xffffffffu, rm1, 2));
        const float mn0 = fmaxf(m0, rm0);
        const float mn1 = fmaxf(m1, rm1);
        const float sc0 = (m0 == -INFINITY) ? 0.f : __expf(m0 - mn0);
        const float sc1 = (m1 == -INFINITY) ? 0.f : __expf(m1 - mn1);

        float rs0 = 0.f, rs1 = 0.f;
#pragma unroll
        for (int t = 0; t < 4; ++t) {
            const int c = t * 8 + (lane & 3) * 2;
            const float e00 = __expf(s[t][0] - mn0);
            const float e01 = __expf(s[t][1] - mn0);
            const float e10 = __expf(s[t][2] - mn1);
            const float e11 = __expf(s[t][3] - mn1);
            rs0 += e00 + e01;
            rs1 += e10 + e11;
            const float h00 = __bfloat162float(__float2bfloat16(e00));
            const float h01 = __bfloat162float(__float2bfloat16(e01));
            const float h10 = __bfloat162float(__float2bfloat16(e10));
            const float h11 = __bfloat162float(__float2bfloat16(e11));
            char* p0 = smem + (wm * 16 + r0) * PROWB + c * 2;
            char* p1 = smem + (wm * 16 + r0 + 8) * PROWB + c * 2;
            *(uint32_t*)(p0 + OFF_PHI) = packbf(e00, e01);
            *(uint32_t*)(p0 + OFF_PLO) = packbf(e00 - h00, e01 - h01);
            *(uint32_t*)(p1 + OFF_PHI) = packbf(e10, e11);
            *(uint32_t*)(p1 + OFF_PLO) = packbf(e10 - h10, e11 - h11);
        }
        rs0 += __shfl_xor_sync(0xffffffffu, rs0, 1);
        rs0 += __shfl_xor_sync(0xffffffffu, rs0, 2);
        rs1 += __shfl_xor_sync(0xffffffffu, rs1, 1);
        rs1 += __shfl_xor_sync(0xffffffffu, rs1, 2);
        l0 = l0 * sc0 + rs0; m0 = mn0;
        l1 = l1 * sc1 + rs1; m1 = mn1;

#pragma unroll
        for (int t = 0; t < 16; ++t) {
            o[t][0] *= sc0; o[t][1] *= sc0;
            o[t][2] *= sc1; o[t][3] *= sc1;
        }
        __syncwarp();

        const uint32_t vbh = sb + OFF_VHI + (kt & 1) * KSTGB;
        const uint32_t vbl = sb + OFF_VLO + (kt & 1) * KSTGB;
#pragma unroll
        for (int ks = 0; ks < 2; ++ks) {
            uint32_t ph[4], pl[4];
            ldsm4(ph, sb + OFF_PHI + poff + ks * 32);
            ldsm4(pl, sb + OFF_PLO + poff + ks * 32);
#pragma unroll
            for (int nb = 0; nb < 8; ++nb) {
                uint32_t vh[4], vl[4];
                const uint32_t va = (ks * 16) * QROWB + vfr + nb * 32;
                ldsm4t(vh, vbh + va);
                ldsm4t(vl, vbl + va);
#pragma unroll
                for (int half = 0; half < 2; ++half) {
                    const int t = nb * 2 + half;
                    const int off = half * 2;
                    mma_bf16(o[t], ph, &vh[off]);
                    mma_bf16(o[t], ph, &vl[off]);
                    mma_bf16(o[t], pl, &vh[off]);
                }
            }
        }
    }

    // ---- epilogue: normalize, store fp32 to g_q (attn output) ----
    const float inv0 = 1.f / l0;
    const float inv1 = 1.f / l1;
    const size_t row0 = ((size_t)b * SEQ + q0 + wm * 16 + r0) * EMB + h * HD;
    const size_t row1 = row0 + (size_t)8 * EMB;
#pragma unroll
    for (int t = 0; t < 16; ++t) {
        const int c = t * 8 + (lane & 3) * 2;
        float2 v0, v1;
        v0.x = o[t][0] * inv0; v0.y = o[t][1] * inv0;
        v1.x = o[t][2] * inv1; v1.y = o[t][3] * inv1;
        *(float2*)(g_q + row0 + c) = v0;
        *(float2*)(g_q + row1 + c) = v1;
    }
}

// =================================================================
extern "C" void kernel_launch(void* const* d_in, const int* in_sizes, int n_in,
                              void* d_out, int out_size)
{
    const float* X    = (const float*)d_in[0];
    const int*   mask = (const int*)d_in[1];
    const float* Wqkv = (const float*)d_in[2];
    const float* bqkv = (const float*)d_in[3];
    const float* Wo   = (const float*)d_in[4];
    const float* bo   = (const float*)d_in[5];
    float* out = (float*)d_out;

    int8_t *a0, *a1, *w10, *w11, *w20, *w21;
    float *sa, *sw1, *sw2, *gq;
    cudaGetSymbolAddress((void**)&a0,  g_a0);
    cudaGetSymbolAddress((void**)&a1,  g_a1);
    cudaGetSymbolAddress((void**)&sa,  g_sa);
    cudaGetSymbolAddress((void**)&w10, g_w10);
    cudaGetSymbolAddress((void**)&w11, g_w11);
    cudaGetSymbolAddress((void**)&sw1, g_sw1);
    cudaGetSymbolAddress((void**)&w20, g_w20);
    cudaGetSymbolAddress((void**)&w21, g_w21);
    cudaGetSymbolAddress((void**)&sw2, g_sw2);
    cudaGetSymbolAddress((void**)&gq,  g_q);

    cudaFuncSetAttribute(gemm_i8<0>, cudaFuncAttributeMaxDynamicSharedMemorySize, GEMM_SMEM);
    cudaFuncSetAttribute(gemm_i8<1>, cudaFuncAttributeMaxDynamicSharedMemorySize, GEMM_SMEM);
    cudaFuncSetAttribute(attn_mma, cudaFuncAttributeMaxDynamicSharedMemorySize, ATTN_SMEM);

    // 1) quantize X, Wqkv, Wo; rope table
    quant_rows<<<MROWS, 256>>>(X, a0, a1, sa, GK);
    quant_rows<<<NQKV, 256>>>(Wqkv, w10, w11, sw1, GK);
    quant_rows<<<EMB, 256>>>(Wo, w20, w21, sw2, GK);
    rope_table<<<SEQ, HD>>>();

    // 2) QKV projection (int8 2-level): Q,K fp32, V bf16 hi/lo
    gemm_i8<1><<<dim3(NQKV / 128, MROWS / 128), 256, GEMM_SMEM>>>(
        a0, a1, sa, w10, w11, sw1, bqkv, nullptr, NQKV);

    // 3) RoPE + Q-scale + bf16 split
    rope_apply<<<BATCH * NH * SEQ, HD>>>();

    // 4) MMA flash attention (bf16x3) -> fp32 attn-out in g_q
    attn_mma<<<dim3(SEQ / 128, NH, BATCH), 256, ATTN_SMEM>>>(mask);

    // 5) quantize attn-out, then output projection (int8 2-level)
    quant_rows<<<MROWS, 256>>>(gq, a0, a1, sa, GK);
    gemm_i8<0><<<dim3(EMB / 128, MROWS / 128), 256, GEMM_SMEM>>>(
        a0, a1, sa, w20, w21, sw2, bo, out, EMB);
}

// round 17
// speedup vs baseline: 1.9409x; 1.9409x over previous
#include <cuda_runtime.h>
#include <cuda_bf16.h>
#include <math.h>
#include <stdint.h>

#define BATCH 2
#define SEQ   2048
#define EMB   2048
#define NH    16
#define HD    128
#define NQKV  6144
#define MROWS 4096
#define GK    2048
#define NSTG  (GK / 32)     // 64 stages of BK=32

// ---------------- scratch (no allocation allowed) ----------------
__device__ float g_q[BATCH * NH * SEQ * HD];     // fp32 Q pre-rope
__device__ float g_k[BATCH * NH * SEQ * HD];     // fp32 K pre-rope

__device__ __nv_bfloat16 g_qhi[BATCH * NH * SEQ * HD];
__device__ __nv_bfloat16 g_qlo[BATCH * NH * SEQ * HD];
__device__ __nv_bfloat16 g_khi[BATCH * NH * SEQ * HD];
__device__ __nv_bfloat16 g_klo[BATCH * NH * SEQ * HD];
__device__ __nv_bfloat16 g_vhi[BATCH * NH * SEQ * HD];
__device__ __nv_bfloat16 g_vlo[BATCH * NH * SEQ * HD];

__device__ __nv_bfloat16 g_ahi[MROWS * GK];     // X hi, later attn-out hi
__device__ __nv_bfloat16 g_alo[MROWS * GK];
__device__ __nv_bfloat16 g_w1hi[NQKV * GK];
__device__ __nv_bfloat16 g_w1lo[NQKV * GK];
__device__ __nv_bfloat16 g_w2hi[EMB * GK];
__device__ __nv_bfloat16 g_w2lo[EMB * GK];

__device__ float g_cs[SEQ * HD];
__device__ float g_sn[SEQ * HD];

// ================= family-generic PTX helpers ====================
__device__ __forceinline__ uint32_t smem_u32(const void* p) {
    uint32_t a;
    asm("{ .reg .u64 t; cvta.to.shared.u64 t, %1; cvt.u32.u64 %0, t; }" : "=r"(a) : "l"(p));
    return a;
}
#define CP_ASYNC16(s, g) \
    asm volatile("cp.async.cg.shared.global [%0], [%1], 16;" :: "r"(s), "l"(g))
#define CP_COMMIT() asm volatile("cp.async.commit_group;" ::: "memory")
#define CP_WAIT1()  asm volatile("cp.async.wait_group 1;" ::: "memory")
#define CP_WAIT0()  asm volatile("cp.async.wait_group 0;" ::: "memory")

__device__ __forceinline__ void ldsm4(uint32_t* r, uint32_t addr) {
    asm volatile("ldmatrix.sync.aligned.m8n8.x4.shared.b16 {%0,%1,%2,%3}, [%4];"
        : "=r"(r[0]), "=r"(r[1]), "=r"(r[2]), "=r"(r[3]) : "r"(addr));
}
__device__ __forceinline__ void ldsm4t(uint32_t* r, uint32_t addr) {
    asm volatile("ldmatrix.sync.aligned.m8n8.x4.trans.shared.b16 {%0,%1,%2,%3}, [%4];"
        : "=r"(r[0]), "=r"(r[1]), "=r"(r[2]), "=r"(r[3]) : "r"(addr));
}
__device__ __forceinline__ void mma_bf16(float* c, const uint32_t* a, const uint32_t* b) {
    asm volatile(
        "mma.sync.aligned.m16n8k16.row.col.f32.bf16.bf16.f32 "
        "{%0,%1,%2,%3}, {%4,%5,%6,%7}, {%8,%9}, {%0,%1,%2,%3};"
        : "+f"(c[0]), "+f"(c[1]), "+f"(c[2]), "+f"(c[3])
        : "r"(a[0]), "r"(a[1]), "r"(a[2]), "r"(a[3]), "r"(b[0]), "r"(b[1]));
}
__device__ __forceinline__ uint32_t packbf(float a, float b) {
    __nv_bfloat162 t;
    t.x = __float2bfloat16(a);
    t.y = __float2bfloat16(b);
    return *reinterpret_cast<uint32_t*>(&t);
}

// ================= fp32 -> bf16 hi/lo split ======================
__global__ void cvt_split(const float* __restrict__ x,
                          __nv_bfloat16* __restrict__ hi,
                          __nv_bfloat16* __restrict__ lo, int n)
{
    int i = (blockIdx.x * blockDim.x + threadIdx.x) * 4;
    if (i >= n) return;
    float4 v = *(const float4*)(x + i);
    __nv_bfloat16 h0 = __float2bfloat16(v.x);
    __nv_bfloat16 h1 = __float2bfloat16(v.y);
    __nv_bfloat16 h2 = __float2bfloat16(v.z);
    __nv_bfloat16 h3 = __float2bfloat16(v.w);
    __nv_bfloat16 l0 = __float2bfloat16(v.x - __bfloat162float(h0));
    __nv_bfloat16 l1 = __float2bfloat16(v.y - __bfloat162float(h1));
    __nv_bfloat16 l2 = __float2bfloat16(v.z - __bfloat162float(h2));
    __nv_bfloat16 l3 = __float2bfloat16(v.w - __bfloat162float(h3));
    __nv_bfloat162 a, b, c, d;
    a.x = h0; a.y = h1; b.x = h2; b.y = h3;
    c.x = l0; c.y = l1; d.x = l2; d.y = l3;
    *(__nv_bfloat162*)(hi + i)     = a;
    *(__nv_bfloat162*)(hi + i + 2) = b;
    *(__nv_bfloat162*)(lo + i)     = c;
    *(__nv_bfloat162*)(lo + i + 2) = d;
}

// =================================================================
// mma.sync bf16x3 GEMM (R10 config): CTA 128x256, 8 warps of 64x64,
// BK=32, double-buffered cp.async.
// =================================================================
#define SROWB 80
#define ATILE (128 * SROWB)
#define BTILE (256 * SROWB)
#define STAGEB (2 * ATILE + 2 * BTILE)
#define GEMM_SMEM (2 * STAGEB)

template <int MODE>
__global__ void __launch_bounds__(256, 1)
gemm_mma(const __nv_bfloat16* __restrict__ Ahi, const __nv_bfloat16* __restrict__ Alo,
         const __nv_bfloat16* __restrict__ Bhi, const __nv_bfloat16* __restrict__ Blo,
         const float* __restrict__ bias, float* __restrict__ C, int Ndim)
{
    extern __shared__ char smem[];
    const uint32_t sb = smem_u32(smem);
    const int tid = threadIdx.x;
    const int lane = tid & 31, wid = tid >> 5;
    const int wm = wid >> 2, wn = wid & 3;
    const int bm = blockIdx.y * 128, bn = blockIdx.x * 256;

    const char* gA0 = (const char*)(Ahi + (size_t)bm * GK);
    const char* gA1 = (const char*)(Alo + (size_t)bm * GK);
    const char* gB0 = (const char*)(Bhi + (size_t)bn * GK);
    const char* gB1 = (const char*)(Blo + (size_t)bn * GK);

    uint32_t arow[4];
#pragma unroll
    for (int mt = 0; mt < 4; ++mt)
        arow[mt] = (uint32_t)((wm * 64 + mt * 16 + (lane & 15)) * SROWB + ((lane >> 4) << 4));
    uint32_t brow[4];
#pragma unroll
    for (int nb = 0; nb < 4; ++nb)
        brow[nb] = (uint32_t)((wn * 64 + nb * 16 + ((lane >> 4) << 3) + (lane & 7)) * SROWB
                              + (((lane >> 3) & 1) << 4));

    float acc[4][8][4];
#pragma unroll
    for (int i = 0; i < 4; ++i)
#pragma unroll
        for (int j = 0; j < 8; ++j)
#pragma unroll
            for (int k = 0; k < 4; ++k) acc[i][j][k] = 0.f;

    auto issue_load = [&](int stage, int buf) {
        const size_t kb = (size_t)stage * 64;
        const uint32_t base = sb + buf * STAGEB;
#pragma unroll
        for (int r = 0; r < 2; ++r) {
            const int idx = tid + r * 256;
            const int row = idx >> 2;
            const int seg = (idx & 3) * 16;
            const size_t go = (size_t)row * (GK * 2) + kb + seg;
            const uint32_t so = row * SROWB + seg;
            CP_ASYNC16(base + 0     + so, gA0 + go);
            CP_ASYNC16(base + ATILE + so, gA1 + go);
        }
#pragma unroll
        for (int r = 0; r < 4; ++r) {
            const int idx = tid + r * 256;
            const int row = idx >> 2;
            const int seg = (idx & 3) * 16;
            const size_t go = (size_t)row * (GK * 2) + kb + seg;
            const uint32_t so = row * SROWB + seg;
            CP_ASYNC16(base + 2 * ATILE         + so, gB0 + go);
            CP_ASYNC16(base + 2 * ATILE + BTILE + so, gB1 + go);
        }
        CP_COMMIT();
    };

    issue_load(0, 0);

    for (int s = 0; s < NSTG; ++s) {
        if (s + 1 < NSTG) {
            issue_load(s + 1, (s + 1) & 1);
            CP_WAIT1();
        } else {
            CP_WAIT0();
        }
        __syncthreads();

        const uint32_t base = sb + (s & 1) * STAGEB;
        const uint32_t abase = base;
        const uint32_t bbase = base + 2 * ATILE;
#pragma unroll
        for (int step = 0; step < 2; ++step) {
            const uint32_t ko = step * 32;
            uint32_t bh[4][4], bl[4][4];
#pragma unroll
            for (int nb = 0; nb < 4; ++nb) {
                ldsm4(bh[nb], bbase + brow[nb] + ko);
                ldsm4(bl[nb], bbase + BTILE + brow[nb] + ko);
            }
#pragma unroll
            for (int mt = 0; mt < 4; ++mt) {
                uint32_t ah[4], al[4];
                ldsm4(ah, abase + arow[mt] + ko);
                ldsm4(al, abase + ATILE + arow[mt] + ko);
#pragma unroll
                for (int n8 = 0; n8 < 8; ++n8) {
                    const int nb = n8 >> 1, off = (n8 & 1) * 2;
                    mma_bf16(acc[mt][n8], ah, &bh[nb][off]);
                    mma_bf16(acc[mt][n8], ah, &bl[nb][off]);
                    mma_bf16(acc[mt][n8], al, &bh[nb][off]);
                }
            }
        }
        __syncthreads();
    }

    // ---------------- epilogue ----------------
#pragma unroll
    for (int mt = 0; mt < 4; ++mt) {
#pragma unroll
        for (int n8 = 0; n8 < 8; ++n8) {
            const int gm0 = bm + wm * 64 + mt * 16 + (lane >> 2);
            const int gn  = bn + wn * 64 + n8 * 8 + (lane & 3) * 2;
            const float2 bv = *(const float2*)(bias + gn);
            float2 v0, v1;
            v0.x = acc[mt][n8][0] + bv.x; v0.y = acc[mt][n8][1] + bv.y;
            v1.x = acc[mt][n8][2] + bv.x; v1.y = acc[mt][n8][3] + bv.y;
            if (MODE == 0) {
                *(float2*)(C + (size_t)gm0 * Ndim + gn)       = v0;
                *(float2*)(C + (size_t)(gm0 + 8) * Ndim + gn) = v1;
            } else {
                const int which = gn >> 11;                  // 0=Q,1=K,2=V
                const int hh = (gn >> 7) & 15;
                const int dd = (gn & 127);
                const int b0 = gm0 >> 11, s0 = gm0 & 2047;
                const int gm1 = gm0 + 8;
                const int b1 = gm1 >> 11, s1 = gm1 & 2047;
                const size_t o0 = (((size_t)(b0 * NH + hh) * SEQ + s0) * HD) + dd;
                const size_t o1 = (((size_t)(b1 * NH + hh) * SEQ + s1) * HD) + dd;
                if (which == 2) {
                    float h0 = __bfloat162float(__float2bfloat16(v0.x));
                    float h1 = __bfloat162float(__float2bfloat16(v0.y));
                    float h2 = __bfloat162float(__float2bfloat16(v1.x));
                    float h3 = __bfloat162float(__float2bfloat16(v1.y));
                    *(uint32_t*)(g_vhi + o0) = packbf(v0.x, v0.y);
                    *(uint32_t*)(g_vlo + o0) = packbf(v0.x - h0, v0.y - h1);
                    *(uint32_t*)(g_vhi + o1) = packbf(v1.x, v1.y);
                    *(uint32_t*)(g_vlo + o1) = packbf(v1.x - h2, v1.y - h3);
                } else {
                    float* tgt = (which == 0) ? g_q : g_k;
                    *(float2*)(tgt + o0) = v0;
                    *(float2*)(tgt + o1) = v1;
                }
            }
        }
    }
}

// =================================================================
// RoPE: table in fp32 (reference computes freqs in fp32 too).
// =================================================================
__global__ void rope_table()
{
    const int s = blockIdx.x, d = threadIdx.x;
    const int i = d >> 1;
    const float ang = (float)exp(-((double)(2 * i) / 2048.0) * 9.210340371976184);
    const float fr = (float)s * ang;
    g_cs[s * HD + d] = cosf(fr);
    g_sn[s * HD + d] = sinf(fr);
}

__global__ void rope_apply()
{
    __shared__ float rq[HD], rk[HD];
    const int row = blockIdx.x;            // (b*NH+h)*SEQ + s
    const int s = row & (SEQ - 1);
    const int d = threadIdx.x;
    rq[d] = g_q[(size_t)row * HD + d];
    rk[d] = g_k[(size_t)row * HD + d];
    __syncthreads();

    const float c  = g_cs[s * HD + d];
    const float sn = g_sn[s * HD + d];
    float oq, ok;
    if (d < 64) {
        oq = c * rq[d] - sn * rq[2 * d + 1];
        ok = c * rk[d] - sn * rk[2 * d + 1];
    } else {
        const int j = d - 64;
        oq = c * rq[d] + sn * rq[2 * j];
        ok = c * rk[d] + sn * rk[2 * j];
    }
    const float qs = oq * 0.08838834764831845f;   // fold 1/sqrt(HD)
    const size_t idx = (size_t)row * HD + d;
    __nv_bfloat16 qh = __float2bfloat16(qs);
    g_qhi[idx] = qh;
    g_qlo[idx] = __float2bfloat16(qs - __bfloat162float(qh));
    __nv_bfloat16 kh = __float2bfloat16(ok);
    g_khi[idx] = kh;
    g_klo[idx] = __float2bfloat16(ok - __bfloat162float(kh));
}

// =================================================================
// MMA flash attention, bf16x3, Q frags in registers, AKB=64 keys
// per block. P tiles alias the Q staging region (Q is hoisted).
// =================================================================
#define AKB   64
#define QROWB 272
#define PROWB 144
#define KSTGB (AKB * QROWB)              // 17408
#define OFF_QHI 0
#define OFF_QLO 34816
#define OFF_PHI 0                        // alias Q region (post-hoist)
#define OFF_PLO 18432
#define OFF_KHI 69632
#define OFF_KLO (OFF_KHI + 2 * KSTGB)    // 104448
#define OFF_VHI (OFF_KLO + 2 * KSTGB)    // 139264
#define OFF_VLO (OFF_VHI + 2 * KSTGB)    // 174080
#define OFF_MSK (OFF_VLO + 2 * KSTGB)    // 208896
#define ATTN_SMEM (OFF_MSK + 256)        // 209152

__global__ void __launch_bounds__(256, 1)
attn_mma(const int* __restrict__ mask)
{
    extern __shared__ char smem[];
    const uint32_t sb = smem_u32(smem);
    const int tid = threadIdx.x;
    const int lane = tid & 31, wm = tid >> 5;
    const int q0 = blockIdx.x * 128;
    const int h = blockIdx.y, b = blockIdx.z;
    const size_t bh = ((size_t)b * NH + h) * SEQ;

    // ---- load Q tile (hi+lo) ----
    {
        const char* gqh = (const char*)(g_qhi + (bh + q0) * HD);
        const char* gql = (const char*)(g_qlo + (bh + q0) * HD);
#pragma unroll
        for (int i = 0; i < 8; ++i) {
            const int c = tid + i * 256;
            const int row = c >> 4, seg = (c & 15) * 16;
            CP_ASYNC16(sb + OFF_QHI + row * QROWB + seg, gqh + (size_t)row * 256 + seg);
            CP_ASYNC16(sb + OFF_QLO + row * QROWB + seg, gql + (size_t)row * 256 + seg);
        }
        CP_COMMIT();
    }
    auto loadKV = [&](int kt) {
        const int st = kt & 1;
        const char* gkh = (const char*)(g_khi + (bh + kt * AKB) * HD);
        const char* gkl = (const char*)(g_klo + (bh + kt * AKB) * HD);
        const char* gvh = (const char*)(g_vhi + (bh + kt * AKB) * HD);
        const char* gvl = (const char*)(g_vlo + (bh + kt * AKB) * HD);
#pragma unroll
        for (int i = 0; i < 4; ++i) {
            const int c = tid + i * 256;          // 0..1023
            const int row = c >> 4, seg = (c & 15) * 16;
            const uint32_t so = st * KSTGB + row * QROWB + seg;
            const size_t go = (size_t)row * 256 + seg;
            CP_ASYNC16(sb + OFF_KHI + so, gkh + go);
            CP_ASYNC16(sb + OFF_KLO + so, gkl + go);
            CP_ASYNC16(sb + OFF_VHI + so, gvh + go);
            CP_ASYNC16(sb + OFF_VLO + so, gvl + go);
        }
        CP_COMMIT();
    };
    loadKV(0);

    const int r0 = lane >> 2;
    const uint32_t qoff = (wm * 16 + (lane & 15)) * QROWB + ((lane >> 4) << 4);
    const uint32_t kfr = (((lane >> 4) << 3) + (lane & 7)) * QROWB + (((lane >> 3) & 1) << 4);
    const uint32_t poff = (wm * 16 + (lane & 15)) * PROWB + ((lane >> 4) << 4);
    const uint32_t vfr = (lane & 15) * QROWB + ((lane >> 4) << 4);

    // ---- hoist Q fragments into registers ----
    CP_WAIT1();            // Q group done (KV0 may be pending)
    __syncthreads();
    uint32_t qh[8][4], ql[8][4];
#pragma unroll
    for (int ks = 0; ks < 8; ++ks) {
        ldsm4(qh[ks], sb + OFF_QHI + qoff + ks * 32);
        ldsm4(ql[ks], sb + OFF_QLO + qoff + ks * 32);
    }

    float o[16][4];
#pragma unroll
    for (int t = 0; t < 16; ++t)
#pragma unroll
        for (int j = 0; j < 4; ++j) o[t][j] = 0.f;
    float m0 = -INFINITY, m1 = -INFINITY, l0 = 0.f, l1 = 0.f;

    float* msk = (float*)(smem + OFF_MSK);

    for (int kt = 0; kt < SEQ / AKB; ++kt) {
        __syncthreads();    // prev iter done reading K/V/msk/P
        if (kt + 1 < SEQ / AKB) loadKV(kt + 1);
        if (tid < AKB) msk[tid] = (float)mask[b * SEQ + kt * AKB + tid];
        if (kt + 1 < SEQ / AKB) { CP_WAIT1(); } else { CP_WAIT0(); }
        __syncthreads();

        const uint32_t kbh = sb + OFF_KHI + (kt & 1) * KSTGB;
        const uint32_t kbl = sb + OFF_KLO + (kt & 1) * KSTGB;

        // ---- S = Q K^T (bf16x3), 16 q-rows x 64 keys per warp ----
        float s[8][4];
#pragma unroll
        for (int t = 0; t < 8; ++t)
#pragma unroll
            for (int j = 0; j < 4; ++j) s[t][j] = 0.f;
#pragma unroll
        for (int ks = 0; ks < 8; ++ks) {
            uint32_t kh[4][4], kl[4][4];
#pragma unroll
            for (int nb = 0; nb < 4; ++nb) {
                ldsm4(kh[nb], kbh + nb * 16 * QROWB + kfr + ks * 32);
                ldsm4(kl[nb], kbl + nb * 16 * QROWB + kfr + ks * 32);
            }
#pragma unroll
            for (int t = 0; t < 8; ++t) {
                const int nb = t >> 1, off = (t & 1) * 2;
                mma_bf16(s[t], qh[ks], &kh[nb][off]);
                mma_bf16(s[t], qh[ks], &kl[nb][off]);
                mma_bf16(s[t], ql[ks], &kh[nb][off]);
            }
        }

        // ---- online softmax (rows in-quad) ----
        float rm0 = -INFINITY, rm1 = -INFINITY;
#pragma unroll
        for (int t = 0; t < 8; ++t) {
            const int c = t * 8 + (lane & 3) * 2;
            const float k0 = msk[c], k1 = msk[c + 1];
            if (k0 == 0.f) { s[t][0] = -1e9f; s[t][2] = -1e9f; }
            if (k1 == 0.f) { s[t][1] = -1e9f; s[t][3] = -1e9f; }
            rm0 = fmaxf(rm0, fmaxf(s[t][0], s[t][1]));
            rm1 = fmaxf(rm1, fmaxf(s[t][2], s[t][3]));
        }
        rm0 = fmaxf(rm0, __shfl_xor_sync(0xffffffffu, rm0, 1));
        rm0 = fmaxf(rm0, __shfl_xor_sync(0xffffffffu, rm0, 2));
        rm1 = fmaxf(rm1, __shfl_xor_sync(0xffffffffu, rm1, 1));
        rm1 = fmaxf(rm1, __shfl_xor_sync(0xffffffffu, rm1, 2));
        const float mn0 = fmaxf(m0, rm0);
        const float mn1 = fmaxf(m1, rm1);
        const float sc0 = (m0 == -INFINITY) ? 0.f : __expf(m0 - mn0);
        const float sc1 = (m1 == -INFINITY) ? 0.f : __expf(m1 - mn1);

        float rs0 = 0.f, rs1 = 0.f;
#pragma unroll
        for (int t = 0; t < 8; ++t) {
            const int c = t * 8 + (lane & 3) * 2;
            const float e00 = __expf(s[t][0] - mn0);
            const float e01 = __expf(s[t][1] - mn0);
            const float e10 = __expf(s[t][2] - mn1);
            const float e11 = __expf(s[t][3] - mn1);
            rs0 += e00 + e01;
            rs1 += e10 + e11;
            const float h00 = __bfloat162float(__float2bfloat16(e00));
            const float h01 = __bfloat162float(__float2bfloat16(e01));
            const float h10 = __bfloat162float(__float2bfloat16(e10));
            const float h11 = __bfloat162float(__float2bfloat16(e11));
            char* p0 = smem + (wm * 16 + r0) * PROWB + c * 2;
            char* p1 = smem + (wm * 16 + r0 + 8) * PROWB + c * 2;
            *(uint32_t*)(p0 + OFF_PHI) = packbf(e00, e01);
            *(uint32_t*)(p0 + OFF_PLO) = packbf(e00 - h00, e01 - h01);
            *(uint32_t*)(p1 + OFF_PHI) = packbf(e10, e11);
            *(uint32_t*)(p1 + OFF_PLO) = packbf(e10 - h10, e11 - h11);
        }
        rs0 += __shfl_xor_sync(0xffffffffu, rs0, 1);
        rs0 += __shfl_xor_sync(0xffffffffu, rs0, 2);
        rs1 += __shfl_xor_sync(0xffffffffu, rs1, 1);
        rs1 += __shfl_xor_sync(0xffffffffu, rs1, 2);
        l0 = l0 * sc0 + rs0; m0 = mn0;
        l1 = l1 * sc1 + rs1; m1 = mn1;

#pragma unroll
        for (int t = 0; t < 16; ++t) {
            o[t][0] *= sc0; o[t][1] *= sc0;
            o[t][2] *= sc1; o[t][3] *= sc1;
        }
        __syncwarp();

        // ---- O += P V (bf16x3), 4 k16 chunks ----
        const uint32_t vbh = sb + OFF_VHI + (kt & 1) * KSTGB;
        const uint32_t vbl = sb + OFF_VLO + (kt & 1) * KSTGB;
#pragma unroll
        for (int ks = 0; ks < 4; ++ks) {
            uint32_t ph[4], pl[4];
            ldsm4(ph, sb + OFF_PHI + poff + ks * 32);
            ldsm4(pl, sb + OFF_PLO + poff + ks * 32);
#pragma unroll
            for (int nb = 0; nb < 8; ++nb) {
                uint32_t vh[4], vl[4];
                const uint32_t va = (ks * 16) * QROWB + vfr + nb * 32;
                ldsm4t(vh, vbh + va);
                ldsm4t(vl, vbl + va);
#pragma unroll
                for (int half = 0; half < 2; ++half) {
                    const int t = nb * 2 + half;
                    const int off = half * 2;
                    mma_bf16(o[t], ph, &vh[off]);
                    mma_bf16(o[t], ph, &vl[off]);
                    mma_bf16(o[t], pl, &vh[off]);
                }
            }
        }
    }

    // ---- epilogue: normalize, split to bf16 hi/lo, store ----
    const float inv0 = 1.f / l0;
    const float inv1 = 1.f / l1;
    const size_t row0 = ((size_t)b * SEQ + q0 + wm * 16 + r0) * EMB + h * HD;
    const size_t row1 = row0 + (size_t)8 * EMB;
#pragma unroll
    for (int t = 0; t < 16; ++t) {
        const int c = t * 8 + (lane & 3) * 2;
        const float v0 = o[t][0] * inv0, v1 = o[t][1] * inv0;
        const float v2 = o[t][2] * inv1, v3 = o[t][3] * inv1;
        const float h0 = __bfloat162float(__float2bfloat16(v0));
        const float h1 = __bfloat162float(__float2bfloat16(v1));
        const float h2 = __bfloat162float(__float2bfloat16(v2));
        const float h3 = __bfloat162float(__float2bfloat16(v3));
        *(uint32_t*)(g_ahi + row0 + c) = packbf(v0, v1);
        *(uint32_t*)(g_alo + row0 + c) = packbf(v0 - h0, v1 - h1);
        *(uint32_t*)(g_ahi + row1 + c) = packbf(v2, v3);
        *(uint32_t*)(g_alo + row1 + c) = packbf(v2 - h2, v3 - h3);
    }
}

// =================================================================
extern "C" void kernel_launch(void* const* d_in, const int* in_sizes, int n_in,
                              void* d_out, int out_size)
{
    const float* X    = (const float*)d_in[0];
    const int*   mask = (const int*)d_in[1];
    const float* Wqkv = (const float*)d_in[2];
    const float* bqkv = (const float*)d_in[3];
    const float* Wo   = (const float*)d_in[4];
    const float* bo   = (const float*)d_in[5];
    float* out = (float*)d_out;

    __nv_bfloat16 *ahi, *alo, *w1hi, *w1lo, *w2hi, *w2lo;
    cudaGetSymbolAddress((void**)&ahi,  g_ahi);
    cudaGetSymbolAddress((void**)&alo,  g_alo);
    cudaGetSymbolAddress((void**)&w1hi, g_w1hi);
    cudaGetSymbolAddress((void**)&w1lo, g_w1lo);
    cudaGetSymbolAddress((void**)&w2hi, g_w2hi);
    cudaGetSymbolAddress((void**)&w2lo, g_w2lo);

    cudaFuncSetAttribute(gemm_mma<0>, cudaFuncAttributeMaxDynamicSharedMemorySize, GEMM_SMEM);
    cudaFuncSetAttribute(gemm_mma<1>, cudaFuncAttributeMaxDynamicSharedMemorySize, GEMM_SMEM);
    cudaFuncSetAttribute(attn_mma, cudaFuncAttributeMaxDynamicSharedMemorySize, ATTN_SMEM);

    // 1) conversions + rope table
    cvt_split<<<(MROWS * GK) / 1024, 256>>>(X, ahi, alo, MROWS * GK);
    cvt_split<<<(NQKV * GK) / 1024, 256>>>(Wqkv, w1hi, w1lo, NQKV * GK);
    cvt_split<<<(EMB * GK) / 1024, 256>>>(Wo, w2hi, w2lo, EMB * GK);
    rope_table<<<SEQ, HD>>>();

    // 2) QKV projection: CTA 128x256, bf16x3
    gemm_mma<1><<<dim3(NQKV / 256, MROWS / 128), 256, GEMM_SMEM>>>(
        ahi, alo, w1hi, w1lo, bqkv, nullptr, NQKV);

    // 3) RoPE + Q-scale + bf16 split
    rope_apply<<<BATCH * NH * SEQ, HD>>>();

    // 4) MMA flash attention -> writes g_ahi/g_alo directly
    attn_mma<<<dim3(SEQ / 128, NH, BATCH), 256, ATTN_SMEM>>>(mask);

    // 5) output projection
    gemm_mma<0><<<dim3(EMB / 256, MROWS / 128), 256, GEMM_SMEM>>>(
        ahi, alo, w2hi, w2lo, bo, out, EMB);
}